// round 2
// baseline (speedup 1.0000x reference)
#include <cuda_runtime.h>
#include <math_constants.h>

// Scalar damped-Newton minimization of a degree-6 polynomial.
// Mirrors the JAX reference:
//   d1 = p', d2 = p''
//   loop while g2 > 1e-12 && it < 100:
//     g = d1(x); h = d2(x)
//     step = h > 0 ? g/h : 0.1*g
//     x -= step; g2 = d1(x)^2
// Entirely serial -> one thread, all in registers.

#define MAX_ITER 100
#define GRAD_SQ_TOL 1e-12f

__device__ __forceinline__ float horner(const float* c, int n, float x) {
    // c is lowest-degree-first, n coefficients
    float r = c[n - 1];
    #pragma unroll
    for (int i = n - 2; i >= 0; --i) {
        r = fmaf(r, x, c[i]);
    }
    return r;
}

__global__ void polymin_kernel(const float* __restrict__ poly,
                               const float* __restrict__ x_init,
                               float* __restrict__ out) {
    // 7 coefficients, lowest-degree-first
    float c[7];
    #pragma unroll
    for (int i = 0; i < 7; ++i) c[i] = poly[i];

    // first derivative: d1[i] = c[i+1] * (i+1), 6 coeffs
    float d1[6];
    #pragma unroll
    for (int i = 0; i < 6; ++i) d1[i] = c[i + 1] * (float)(i + 1);

    // second derivative: d2[i] = d1[i+1] * (i+1), 5 coeffs
    float d2[5];
    #pragma unroll
    for (int i = 0; i < 5; ++i) d2[i] = d1[i + 1] * (float)(i + 1);

    float x = x_init[0];
    float g2 = CUDART_INF_F;  // first cond check: inf > tol -> always enter

    for (int it = 0; it < MAX_ITER; ++it) {
        if (!(g2 > GRAD_SQ_TOL)) break;
        float g = horner(d1, 6, x);
        float h = horner(d2, 5, x);
        float step = (h > 0.0f) ? (g / h) : (0.1f * g);
        x = x - step;
        float gn = horner(d1, 6, x);
        g2 = gn * gn;
    }

    out[0] = x;
}

extern "C" void kernel_launch(void* const* d_in, const int* in_sizes, int n_in,
                              void* d_out, int out_size) {
    const float* poly   = (const float*)d_in[0];   // 7 fp32
    const float* x_init = (const float*)d_in[1];   // 1 fp32
    float* out = (float*)d_out;                    // 1 fp32
    polymin_kernel<<<1, 1>>>(poly, x_init, out);
}